// round 1
// baseline (speedup 1.0000x reference)
#include <cuda_runtime.h>
#include <math.h>
#include <limits.h>

#define NN   50000
#define EE   800000
#define ETOT 850000   // E + N self loops
#define GG   512
#define HH   4
#define CC   64
#define HC   256      // H*C
#define DIN_ 128
#define DENC_ 256

// ---------------- scratch (static device arrays; no allocation) ----------------
__device__ float g_xl[NN * HC];      // 51.2 MB
__device__ float g_xr[NN * HC];      // 51.2 MB
__device__ float g_e[ETOT * HH];     // 13.6 MB (logits, then exp(a) in-place)
__device__ int   g_m[NN * HH];       // per-dst-head max (ordered-int encoded)
__device__ float g_den[NN * HH];     // softmax denominators
__device__ float g_hacc[NN * CC];    // head-mean aggregated messages
__device__ float g_pool[GG * CC];    // per-graph sums
__device__ int   g_cnt[GG];          // per-graph node counts

// ---------------- f32x2 packed-math helpers (sm_103a FFMA2) ----------------
__device__ __forceinline__ unsigned long long pack2(float x, float y) {
    unsigned long long r;
    asm("mov.b64 %0, {%1,%2};" : "=l"(r) : "f"(x), "f"(y));
    return r;
}
__device__ __forceinline__ void unpack2(unsigned long long v, float& x, float& y) {
    asm("mov.b64 {%0,%1}, %2;" : "=f"(x), "=f"(y) : "l"(v));
}
__device__ __forceinline__ unsigned long long fma2(unsigned long long a,
                                                   unsigned long long b,
                                                   unsigned long long c) {
    unsigned long long d;
    asm("fma.rn.f32x2 %0, %1, %2, %3;" : "=l"(d) : "l"(a), "l"(b), "l"(c));
    return d;
}

// float <-> monotone ordered int (for atomicMax on floats)
__device__ __forceinline__ int fenc(float f) {
    int i = __float_as_int(f);
    return i >= 0 ? i : (i ^ 0x7fffffff);
}
__device__ __forceinline__ float fdec(int i) {
    return __int_as_float(i >= 0 ? i : (i ^ 0x7fffffff));
}

// ---------------- K0: init scratch ----------------
__global__ void k_init() {
    int i = blockIdx.x * blockDim.x + threadIdx.x;
    int stride = gridDim.x * blockDim.x;
    for (int j = i; j < NN * CC; j += stride) g_hacc[j] = 0.f;
    for (int j = i; j < NN * HH; j += stride) { g_m[j] = INT_MIN; g_den[j] = 0.f; }
    for (int j = i; j < GG * CC; j += stride) g_pool[j] = 0.f;
    for (int j = i; j < GG; j += stride) g_cnt[j] = 0;
}

// ---------------- K1: xl = x@Wl+bl, xr = x@Wr+br (blockIdx.z selects) ----------------
// BM=BN=128, BK=16, 256 threads, 8x8 microtile, FFMA2 inner loop.
__global__ __launch_bounds__(256) void k_gemm(const float* __restrict__ x,
                                              const float* __restrict__ Wl,
                                              const float* __restrict__ bl,
                                              const float* __restrict__ Wr,
                                              const float* __restrict__ br) {
    const float* W    = blockIdx.z ? Wr : Wl;
    const float* bias = blockIdx.z ? br : bl;
    float* out        = blockIdx.z ? g_xr : g_xl;

    __shared__ unsigned long long As2[16][128]; // a duplicated-packed: 16 KB
    __shared__ float Bs[16][128];               // 8 KB

    const int tid = threadIdx.x;
    const int tx = tid & 15, ty = tid >> 4;
    const int bm = blockIdx.x * 128, bn = blockIdx.y * 128;

    unsigned long long acc[8][4];
#pragma unroll
    for (int r = 0; r < 8; r++)
#pragma unroll
        for (int p = 0; p < 4; p++) acc[r][p] = 0ull;

    const int arow = tid >> 2;         // 0..63
    const int acol = (tid & 3) << 2;   // 0,4,8,12
    const int brow = tid >> 5;         // 0..7
    const int bcol = (tid & 31) << 2;  // 0..124

    for (int k0 = 0; k0 < DIN_; k0 += 16) {
#pragma unroll
        for (int rr = 0; rr < 2; rr++) {
            int r = arow + rr * 64;
            int gm = bm + r;
            float4 v = make_float4(0.f, 0.f, 0.f, 0.f);
            if (gm < NN) v = *(const float4*)&x[gm * DIN_ + k0 + acol];
            As2[acol + 0][r] = pack2(v.x, v.x);
            As2[acol + 1][r] = pack2(v.y, v.y);
            As2[acol + 2][r] = pack2(v.z, v.z);
            As2[acol + 3][r] = pack2(v.w, v.w);
        }
#pragma unroll
        for (int rr = 0; rr < 2; rr++) {
            int r = brow + rr * 8;
            *(float4*)&Bs[r][bcol] = *(const float4*)&W[(k0 + r) * HC + bn + bcol];
        }
        __syncthreads();
#pragma unroll
        for (int kk = 0; kk < 16; kk++) {
            ulonglong2 a01 = *(const ulonglong2*)&As2[kk][ty * 8 + 0];
            ulonglong2 a23 = *(const ulonglong2*)&As2[kk][ty * 8 + 2];
            ulonglong2 a45 = *(const ulonglong2*)&As2[kk][ty * 8 + 4];
            ulonglong2 a67 = *(const ulonglong2*)&As2[kk][ty * 8 + 6];
            ulonglong2 b01 = *(const ulonglong2*)&Bs[kk][tx * 8 + 0];
            ulonglong2 b23 = *(const ulonglong2*)&Bs[kk][tx * 8 + 4];
            unsigned long long av[8] = {a01.x, a01.y, a23.x, a23.y,
                                        a45.x, a45.y, a67.x, a67.y};
            unsigned long long bv[4] = {b01.x, b01.y, b23.x, b23.y};
#pragma unroll
            for (int r = 0; r < 8; r++) {
#pragma unroll
                for (int p = 0; p < 4; p++) acc[r][p] = fma2(av[r], bv[p], acc[r][p]);
            }
        }
        __syncthreads();
    }

    // epilogue: + bias, store
    float bvals[8];
#pragma unroll
    for (int j = 0; j < 8; j++) bvals[j] = bias[bn + tx * 8 + j];
#pragma unroll
    for (int r = 0; r < 8; r++) {
        int gm = bm + ty * 8 + r;
        if (gm < NN) {
            float o[8];
#pragma unroll
            for (int p = 0; p < 4; p++) unpack2(acc[r][p], o[2 * p], o[2 * p + 1]);
#pragma unroll
            for (int j = 0; j < 8; j++) o[j] += bvals[j];
            *(float4*)&out[gm * HC + bn + tx * 8 + 0] = make_float4(o[0], o[1], o[2], o[3]);
            *(float4*)&out[gm * HC + bn + tx * 8 + 4] = make_float4(o[4], o[5], o[6], o[7]);
        }
    }
}

// ---------------- K2: per-edge attention logits + segment max ----------------
// one warp per edge; lane l covers flat elements [8l, 8l+8) of the H*C row
__global__ __launch_bounds__(256) void k_edge(const int* __restrict__ ei,
                                              const float* __restrict__ att) {
    const int lane = threadIdx.x & 31;
    int w = (blockIdx.x * blockDim.x + threadIdx.x) >> 5;
    const int nw = (gridDim.x * blockDim.x) >> 5;

    const float4 at0 = *(const float4*)&att[lane * 8 + 0];
    const float4 at1 = *(const float4*)&att[lane * 8 + 4];

    for (int t = w; t < ETOT; t += nw) {
        int src, dst;
        if (t < EE) { src = ei[t]; dst = ei[EE + t]; }
        else        { src = t - EE; dst = src; }

        const float4* pl = (const float4*)&g_xl[src * HC + lane * 8];
        const float4* pr = (const float4*)&g_xr[dst * HC + lane * 8];
        float4 l0 = pl[0], l1 = pl[1];
        float4 r0 = pr[0], r1 = pr[1];

        float p = 0.f, z;
        z = l0.x + r0.x; p = fmaf(fmaf(0.8f, fmaxf(z, 0.f), 0.2f * z), at0.x, p);
        z = l0.y + r0.y; p = fmaf(fmaf(0.8f, fmaxf(z, 0.f), 0.2f * z), at0.y, p);
        z = l0.z + r0.z; p = fmaf(fmaf(0.8f, fmaxf(z, 0.f), 0.2f * z), at0.z, p);
        z = l0.w + r0.w; p = fmaf(fmaf(0.8f, fmaxf(z, 0.f), 0.2f * z), at0.w, p);
        z = l1.x + r1.x; p = fmaf(fmaf(0.8f, fmaxf(z, 0.f), 0.2f * z), at1.x, p);
        z = l1.y + r1.y; p = fmaf(fmaf(0.8f, fmaxf(z, 0.f), 0.2f * z), at1.y, p);
        z = l1.z + r1.z; p = fmaf(fmaf(0.8f, fmaxf(z, 0.f), 0.2f * z), at1.z, p);
        z = l1.w + r1.w; p = fmaf(fmaf(0.8f, fmaxf(z, 0.f), 0.2f * z), at1.w, p);

        // reduce within each 8-lane head group
        p += __shfl_down_sync(0xffffffffu, p, 4, 8);
        p += __shfl_down_sync(0xffffffffu, p, 2, 8);
        p += __shfl_down_sync(0xffffffffu, p, 1, 8);

        if ((lane & 7) == 0) {
            int h = lane >> 3;
            g_e[t * HH + h] = p;
            atomicMax(&g_m[dst * HH + h], fenc(p));
        }
    }
}

// ---------------- K3: a = exp(e - m[dst]); denom += a (in-place into g_e) ------
__global__ __launch_bounds__(256) void k_soft(const int* __restrict__ ei) {
    int t = blockIdx.x * blockDim.x + threadIdx.x;
    const int stride = gridDim.x * blockDim.x;
    for (; t < ETOT; t += stride) {
        int dst = (t < EE) ? ei[EE + t] : (t - EE);
        float4 e4 = *(const float4*)&g_e[t * HH];
        int4 m4 = *(const int4*)&g_m[dst * HH];
        float a0 = __expf(e4.x - fdec(m4.x));
        float a1 = __expf(e4.y - fdec(m4.y));
        float a2 = __expf(e4.z - fdec(m4.z));
        float a3 = __expf(e4.w - fdec(m4.w));
        *(float4*)&g_e[t * HH] = make_float4(a0, a1, a2, a3);
        atomicAdd(&g_den[dst * HH + 0], a0);
        atomicAdd(&g_den[dst * HH + 1], a1);
        atomicAdd(&g_den[dst * HH + 2], a2);
        atomicAdd(&g_den[dst * HH + 3], a3);
    }
}

// ---------------- K4: head-mean weighted scatter ----------------
// one warp per edge; lane l handles channels 2l, 2l+1 across all 4 heads
__global__ __launch_bounds__(256) void k_agg(const int* __restrict__ ei) {
    const int lane = threadIdx.x & 31;
    int w = (blockIdx.x * blockDim.x + threadIdx.x) >> 5;
    const int nw = (gridDim.x * blockDim.x) >> 5;

    for (int t = w; t < ETOT; t += nw) {
        int src, dst;
        if (t < EE) { src = ei[t]; dst = ei[EE + t]; }
        else        { src = t - EE; dst = src; }

        float4 a4 = *(const float4*)&g_e[t * HH];
        float4 d4 = *(const float4*)&g_den[dst * HH];
        float al0 = a4.x / (d4.x + 1e-16f) * 0.25f;
        float al1 = a4.y / (d4.y + 1e-16f) * 0.25f;
        float al2 = a4.z / (d4.z + 1e-16f) * 0.25f;
        float al3 = a4.w / (d4.w + 1e-16f) * 0.25f;

        const float2* px = (const float2*)&g_xl[src * HC];
        float2 v0 = px[lane + 0];
        float2 v1 = px[lane + 32];
        float2 v2 = px[lane + 64];
        float2 v3 = px[lane + 96];

        float ox = v0.x * al0 + v1.x * al1 + v2.x * al2 + v3.x * al3;
        float oy = v0.y * al0 + v1.y * al1 + v2.y * al2 + v3.y * al3;
        atomicAdd(&g_hacc[dst * CC + lane * 2 + 0], ox);
        atomicAdd(&g_hacc[dst * CC + lane * 2 + 1], oy);
    }
}

// ---------------- K5: finalize node features + global mean pool ----------------
__global__ __launch_bounds__(256) void k_fin(const int* __restrict__ batch,
                                             const float* __restrict__ bgnn) {
    int i = blockIdx.x * blockDim.x + threadIdx.x;
    const int stride = gridDim.x * blockDim.x;
    for (; i < NN * CC; i += stride) {
        int n = i >> 6, c = i & 63;
        float v = g_hacc[i] + bgnn[c];
        v = v > 0.f ? v : 0.01f * v;   // outer leaky_relu(0.01)
        int g = batch[n];
        atomicAdd(&g_pool[g * CC + c], v);
        if (c == 0) atomicAdd(&g_cnt[g], 1);
    }
}

// ---------------- K6: final FC  out[g, :] = [hy[g], hg[g]] @ Wfc + bfc ----------
__global__ __launch_bounds__(256) void k_fc(const float* __restrict__ hy,
                                            const float* __restrict__ Wfc,
                                            const float* __restrict__ bfc,
                                            float* __restrict__ out) {
    const int g = blockIdx.x;
    const int j = threadIdx.x;
    __shared__ float sh[DENC_ + CC];
    sh[j] = hy[g * DENC_ + j];
    if (j < CC) {
        int c = g_cnt[g];
        float cn = c > 0 ? (float)c : 1.f;
        sh[DENC_ + j] = g_pool[g * CC + j] / cn;
    }
    __syncthreads();
    float acc = bfc[j];
#pragma unroll 8
    for (int k = 0; k < DENC_ + CC; k++)
        acc = fmaf(sh[k], Wfc[k * DENC_ + j], acc);
    out[g * DENC_ + j] = acc;
}

// ---------------- launch ----------------
extern "C" void kernel_launch(void* const* d_in, const int* in_sizes, int n_in,
                              void* d_out, int out_size) {
    const float* hy   = (const float*)d_in[0];
    const float* x    = (const float*)d_in[1];
    const int*   ei   = (const int*)d_in[2];
    const int*   batch= (const int*)d_in[3];
    const float* Wl   = (const float*)d_in[4];
    const float* bl   = (const float*)d_in[5];
    const float* Wr   = (const float*)d_in[6];
    const float* br   = (const float*)d_in[7];
    const float* att  = (const float*)d_in[8];
    const float* bgnn = (const float*)d_in[9];
    const float* Wfc  = (const float*)d_in[10];
    const float* bfc  = (const float*)d_in[11];
    float* out = (float*)d_out;

    k_init<<<2048, 256>>>();
    k_gemm<<<dim3((NN + 127) / 128, HC / 128, 2), 256>>>(x, Wl, bl, Wr, br);
    k_edge<<<2368, 256>>>(ei, att);
    k_soft<<<2048, 256>>>(ei);
    k_agg<<<2368, 256>>>(ei);
    k_fin<<<2048, 256>>>(batch, bgnn);
    k_fc<<<GG, 256>>>(hy, Wfc, bfc, out);
}

// round 2
// speedup vs baseline: 1.1084x; 1.1084x over previous
#include <cuda_runtime.h>
#include <math.h>
#include <limits.h>

#define NN   50000
#define EE   800000
#define GG   512
#define HH   4
#define CC   64
#define HC   256      // H*C
#define DIN_ 128
#define DENC_ 256

// ---------------- scratch (static device arrays; no allocation) ----------------
__device__ float g_xl[NN * HC];      // 51.2 MB
__device__ float g_xr[NN * HC];      // 51.2 MB
__device__ int   g_deg[NN];          // in-degree histogram (real edges only)
__device__ int   g_off[NN + 1];      // CSR row offsets
__device__ int   g_woff[NN];         // working copy for scatter
__device__ int   g_csrc[EE];         // CSR: src node per incoming edge
__device__ float g_pool[GG * CC];    // per-graph sums
__device__ int   g_cnt[GG];          // per-graph node counts

// ---------------- f32x2 packed-math helpers (sm_103a FFMA2) ----------------
__device__ __forceinline__ unsigned long long pack2(float x, float y) {
    unsigned long long r;
    asm("mov.b64 %0, {%1,%2};" : "=l"(r) : "f"(x), "f"(y));
    return r;
}
__device__ __forceinline__ void unpack2(unsigned long long v, float& x, float& y) {
    asm("mov.b64 {%0,%1}, %2;" : "=f"(x), "=f"(y) : "l"(v));
}
__device__ __forceinline__ unsigned long long fma2(unsigned long long a,
                                                   unsigned long long b,
                                                   unsigned long long c) {
    unsigned long long d;
    asm("fma.rn.f32x2 %0, %1, %2, %3;" : "=l"(d) : "l"(a), "l"(b), "l"(c));
    return d;
}

// ---------------- K0: init scratch ----------------
__global__ void k_init() {
    int i = blockIdx.x * blockDim.x + threadIdx.x;
    int stride = gridDim.x * blockDim.x;
    for (int j = i; j < NN; j += stride) g_deg[j] = 0;
    for (int j = i; j < GG * CC; j += stride) g_pool[j] = 0.f;
    for (int j = i; j < GG; j += stride) g_cnt[j] = 0;
}

// ---------------- CSR build: histogram ----------------
__global__ void k_hist(const int* __restrict__ ei) {
    int t = blockIdx.x * blockDim.x + threadIdx.x;
    if (t < EE) atomicAdd(&g_deg[ei[EE + t]], 1);
}

// ---------------- CSR build: single-block exclusive scan over 50k counts -----
__global__ __launch_bounds__(1024) void k_scan() {
    __shared__ int warpsum[32];
    const int t = threadIdx.x;
    const int per = (NN + 1023) / 1024;   // 49
    const int base = t * per;
    int sum = 0;
    for (int i = 0; i < per; i++) {
        int idx = base + i;
        if (idx < NN) sum += g_deg[idx];
    }
    const int lane = t & 31, wid = t >> 5;
    int v = sum;
#pragma unroll
    for (int off = 1; off < 32; off <<= 1) {
        int u = __shfl_up_sync(0xffffffffu, v, off);
        if (lane >= off) v += u;
    }
    if (lane == 31) warpsum[wid] = v;
    __syncthreads();
    if (wid == 0) {
        int wv = warpsum[lane];
#pragma unroll
        for (int off = 1; off < 32; off <<= 1) {
            int u = __shfl_up_sync(0xffffffffu, wv, off);
            if (lane >= off) wv += u;
        }
        warpsum[lane] = wv;
    }
    __syncthreads();
    int excl = v - sum + (wid > 0 ? warpsum[wid - 1] : 0);
    int run = excl;
    for (int i = 0; i < per; i++) {
        int idx = base + i;
        if (idx < NN) {
            int c = g_deg[idx];
            g_off[idx] = run;
            g_woff[idx] = run;
            run += c;
        }
    }
    if (t == 1023) g_off[NN] = run;
}

// ---------------- CSR build: scatter src ids ----------------
__global__ void k_scatter(const int* __restrict__ ei) {
    int t = blockIdx.x * blockDim.x + threadIdx.x;
    if (t < EE) {
        int dst = ei[EE + t];
        int pos = atomicAdd(&g_woff[dst], 1);
        g_csrc[pos] = ei[t];
    }
}

// ---------------- K1: xl = x@Wl+bl, xr = x@Wr+br (blockIdx.z selects) ----------
// BM=BN=128, BK=16, 256 threads, 8x8 microtile, FFMA2 inner loop.
__global__ __launch_bounds__(256) void k_gemm(const float* __restrict__ x,
                                              const float* __restrict__ Wl,
                                              const float* __restrict__ bl,
                                              const float* __restrict__ Wr,
                                              const float* __restrict__ br) {
    const float* W    = blockIdx.z ? Wr : Wl;
    const float* bias = blockIdx.z ? br : bl;
    float* out        = blockIdx.z ? g_xr : g_xl;

    __shared__ unsigned long long As2[16][128]; // a duplicated-packed: 16 KB
    __shared__ float Bs[16][128];               // 8 KB

    const int tid = threadIdx.x;
    const int tx = tid & 15, ty = tid >> 4;
    const int bm = blockIdx.x * 128, bn = blockIdx.y * 128;

    unsigned long long acc[8][4];
#pragma unroll
    for (int r = 0; r < 8; r++)
#pragma unroll
        for (int p = 0; p < 4; p++) acc[r][p] = 0ull;

    const int arow = tid >> 2;         // 0..63
    const int acol = (tid & 3) << 2;   // 0,4,8,12
    const int brow = tid >> 5;         // 0..7
    const int bcol = (tid & 31) << 2;  // 0..124

    for (int k0 = 0; k0 < DIN_; k0 += 16) {
#pragma unroll
        for (int rr = 0; rr < 2; rr++) {
            int r = arow + rr * 64;
            int gm = bm + r;
            float4 v = make_float4(0.f, 0.f, 0.f, 0.f);
            if (gm < NN) v = *(const float4*)&x[gm * DIN_ + k0 + acol];
            As2[acol + 0][r] = pack2(v.x, v.x);
            As2[acol + 1][r] = pack2(v.y, v.y);
            As2[acol + 2][r] = pack2(v.z, v.z);
            As2[acol + 3][r] = pack2(v.w, v.w);
        }
#pragma unroll
        for (int rr = 0; rr < 2; rr++) {
            int r = brow + rr * 8;
            *(float4*)&Bs[r][bcol] = *(const float4*)&W[(k0 + r) * HC + bn + bcol];
        }
        __syncthreads();
#pragma unroll
        for (int kk = 0; kk < 16; kk++) {
            ulonglong2 a01 = *(const ulonglong2*)&As2[kk][ty * 8 + 0];
            ulonglong2 a23 = *(const ulonglong2*)&As2[kk][ty * 8 + 2];
            ulonglong2 a45 = *(const ulonglong2*)&As2[kk][ty * 8 + 4];
            ulonglong2 a67 = *(const ulonglong2*)&As2[kk][ty * 8 + 6];
            ulonglong2 b01 = *(const ulonglong2*)&Bs[kk][tx * 8 + 0];
            ulonglong2 b23 = *(const ulonglong2*)&Bs[kk][tx * 8 + 4];
            unsigned long long av[8] = {a01.x, a01.y, a23.x, a23.y,
                                        a45.x, a45.y, a67.x, a67.y};
            unsigned long long bv[4] = {b01.x, b01.y, b23.x, b23.y};
#pragma unroll
            for (int r = 0; r < 8; r++) {
#pragma unroll
                for (int p = 0; p < 4; p++) acc[r][p] = fma2(av[r], bv[p], acc[r][p]);
            }
        }
        __syncthreads();
    }

    float bvals[8];
#pragma unroll
    for (int j = 0; j < 8; j++) bvals[j] = bias[bn + tx * 8 + j];
#pragma unroll
    for (int r = 0; r < 8; r++) {
        int gm = bm + ty * 8 + r;
        if (gm < NN) {
            float o[8];
#pragma unroll
            for (int p = 0; p < 4; p++) unpack2(acc[r][p], o[2 * p], o[2 * p + 1]);
#pragma unroll
            for (int j = 0; j < 8; j++) o[j] += bvals[j];
            *(float4*)&out[gm * HC + bn + tx * 8 + 0] = make_float4(o[0], o[1], o[2], o[3]);
            *(float4*)&out[gm * HC + bn + tx * 8 + 4] = make_float4(o[4], o[5], o[6], o[7]);
        }
    }
}

// ---------------- K2: fused node-centric attention + aggregate + pool ----------
// One warp per dst node. Lane l covers flat elements [8l, 8l+8) of the H*C row
// (head = l>>3, channels (l&7)*8 .. +8 of that head).
// Softmax without max-shift (logits are O(10), exp safe; shift-invariant math).
// out[c] = 0.25 * sum_h ( sum_e a_eh * xl[src][h,c] ) / ( sum_e a_eh )
__global__ __launch_bounds__(256) void k_node(const float* __restrict__ att,
                                              const float* __restrict__ bgnn,
                                              const int* __restrict__ batch) {
    const int lane = threadIdx.x & 31;
    int w = (blockIdx.x * blockDim.x + threadIdx.x) >> 5;
    const int nw = (gridDim.x * blockDim.x) >> 5;

    const float4 at0 = *(const float4*)&att[lane * 8 + 0];
    const float4 at1 = *(const float4*)&att[lane * 8 + 4];

    for (int n = w; n < NN; n += nw) {
        const float4* pr = (const float4*)&g_xr[n * HC + lane * 8];
        const float4 r0 = pr[0], r1 = pr[1];

        float acc[8];
#pragma unroll
        for (int j = 0; j < 8; j++) acc[j] = 0.f;
        float D = 0.f;

        const int beg = g_off[n], end = g_off[n + 1];
        // e == beg-1 encodes the self loop (src = n); then the CSR entries.
        for (int e = beg - 1; e < end; e++) {
            const int src = (e < beg) ? n : g_csrc[e];
            const float4* pl = (const float4*)&g_xl[src * HC + lane * 8];
            const float4 l0 = pl[0], l1 = pl[1];

            float p = 0.f, z;
            z = l0.x + r0.x; p = fmaf(fmaf(0.8f, fmaxf(z, 0.f), 0.2f * z), at0.x, p);
            z = l0.y + r0.y; p = fmaf(fmaf(0.8f, fmaxf(z, 0.f), 0.2f * z), at0.y, p);
            z = l0.z + r0.z; p = fmaf(fmaf(0.8f, fmaxf(z, 0.f), 0.2f * z), at0.z, p);
            z = l0.w + r0.w; p = fmaf(fmaf(0.8f, fmaxf(z, 0.f), 0.2f * z), at0.w, p);
            z = l1.x + r1.x; p = fmaf(fmaf(0.8f, fmaxf(z, 0.f), 0.2f * z), at1.x, p);
            z = l1.y + r1.y; p = fmaf(fmaf(0.8f, fmaxf(z, 0.f), 0.2f * z), at1.y, p);
            z = l1.z + r1.z; p = fmaf(fmaf(0.8f, fmaxf(z, 0.f), 0.2f * z), at1.z, p);
            z = l1.w + r1.w; p = fmaf(fmaf(0.8f, fmaxf(z, 0.f), 0.2f * z), at1.w, p);

            // sum within each 8-lane head group; every lane ends with head sum
            p += __shfl_xor_sync(0xffffffffu, p, 4);
            p += __shfl_xor_sync(0xffffffffu, p, 2);
            p += __shfl_xor_sync(0xffffffffu, p, 1);

            const float a = __expf(p);
            D += a;
            acc[0] = fmaf(a, l0.x, acc[0]);
            acc[1] = fmaf(a, l0.y, acc[1]);
            acc[2] = fmaf(a, l0.z, acc[2]);
            acc[3] = fmaf(a, l0.w, acc[3]);
            acc[4] = fmaf(a, l1.x, acc[4]);
            acc[5] = fmaf(a, l1.y, acc[5]);
            acc[6] = fmaf(a, l1.z, acc[6]);
            acc[7] = fmaf(a, l1.w, acc[7]);
        }

        // normalize per head, then mean across heads (lanes {l, l^8, l^16, l^24})
        const float inv = 1.f / (D + 1e-16f);
        float v[8];
#pragma unroll
        for (int j = 0; j < 8; j++) {
            float t = acc[j] * inv;
            t += __shfl_xor_sync(0xffffffffu, t, 8);
            t += __shfl_xor_sync(0xffffffffu, t, 16);
            v[j] = t;
        }

        if (lane < 8) {
            const int g = batch[n];
            if (lane == 0) atomicAdd(&g_cnt[g], 1);
#pragma unroll
            for (int j = 0; j < 8; j++) {
                const int c = lane * 8 + j;
                float val = 0.25f * v[j] + bgnn[c];
                val = val > 0.f ? val : 0.01f * val;   // outer leaky_relu(0.01)
                atomicAdd(&g_pool[g * CC + c], val);
            }
        }
    }
}

// ---------------- K3: final FC  out[g, :] = [hy[g], hg[g]] @ Wfc + bfc ----------
__global__ __launch_bounds__(256) void k_fc(const float* __restrict__ hy,
                                            const float* __restrict__ Wfc,
                                            const float* __restrict__ bfc,
                                            float* __restrict__ out) {
    const int g = blockIdx.x;
    const int j = threadIdx.x;
    __shared__ float sh[DENC_ + CC];
    sh[j] = hy[g * DENC_ + j];
    if (j < CC) {
        int c = g_cnt[g];
        float cn = c > 0 ? (float)c : 1.f;
        sh[DENC_ + j] = g_pool[g * CC + j] / cn;
    }
    __syncthreads();
    float acc = bfc[j];
#pragma unroll 8
    for (int k = 0; k < DENC_ + CC; k++)
        acc = fmaf(sh[k], Wfc[k * DENC_ + j], acc);
    out[g * DENC_ + j] = acc;
}

// ---------------- launch ----------------
extern "C" void kernel_launch(void* const* d_in, const int* in_sizes, int n_in,
                              void* d_out, int out_size) {
    const float* hy   = (const float*)d_in[0];
    const float* x    = (const float*)d_in[1];
    const int*   ei   = (const int*)d_in[2];
    const int*   batch= (const int*)d_in[3];
    const float* Wl   = (const float*)d_in[4];
    const float* bl   = (const float*)d_in[5];
    const float* Wr   = (const float*)d_in[6];
    const float* br   = (const float*)d_in[7];
    const float* att  = (const float*)d_in[8];
    const float* bgnn = (const float*)d_in[9];
    const float* Wfc  = (const float*)d_in[10];
    const float* bfc  = (const float*)d_in[11];
    float* out = (float*)d_out;

    k_init<<<256, 256>>>();
    k_hist<<<(EE + 255) / 256, 256>>>(ei);
    k_scan<<<1, 1024>>>();
    k_scatter<<<(EE + 255) / 256, 256>>>(ei);
    k_gemm<<<dim3((NN + 127) / 128, HC / 128, 2), 256>>>(x, Wl, bl, Wr, br);
    k_node<<<(NN / 8) + 1, 256>>>(att, bgnn, batch);
    k_fc<<<GG, 256>>>(hy, Wfc, bfc, out);
}

// round 3
// speedup vs baseline: 1.1763x; 1.0613x over previous
#include <cuda_runtime.h>
#include <cuda_fp16.h>
#include <math.h>
#include <limits.h>

#define NN   50000
#define EE   800000
#define GG   512
#define HH   4
#define CC   64
#define HC   256      // H*C
#define DIN_ 128
#define DENC_ 256

// ---------------- scratch (static device arrays; no allocation) ----------------
__device__ __half g_xl[NN * HC];     // 25.6 MB (fp16 node features, source)
__device__ __half g_xr[NN * HC];     // 25.6 MB (fp16 node features, target)
__device__ int   g_deg[NN];          // in-degree histogram (real edges only)
__device__ int   g_off[NN + 1];      // CSR row offsets
__device__ int   g_woff[NN];         // working copy for scatter
__device__ int   g_csrc[EE];         // CSR: src node per incoming edge
__device__ float g_pool[GG * CC];    // per-graph sums
__device__ int   g_cnt[GG];          // per-graph node counts

// ---------------- f32x2 packed-math helpers (sm_103a FFMA2) ----------------
__device__ __forceinline__ unsigned long long pack2(float x, float y) {
    unsigned long long r;
    asm("mov.b64 %0, {%1,%2};" : "=l"(r) : "f"(x), "f"(y));
    return r;
}
__device__ __forceinline__ void unpack2(unsigned long long v, float& x, float& y) {
    asm("mov.b64 {%0,%1}, %2;" : "=f"(x), "=f"(y) : "l"(v));
}
__device__ __forceinline__ unsigned long long fma2(unsigned long long a,
                                                   unsigned long long b,
                                                   unsigned long long c) {
    unsigned long long d;
    asm("fma.rn.f32x2 %0, %1, %2, %3;" : "=l"(d) : "l"(a), "l"(b), "l"(c));
    return d;
}

// ---------------- K0: init scratch ----------------
__global__ void k_init() {
    int i = blockIdx.x * blockDim.x + threadIdx.x;
    int stride = gridDim.x * blockDim.x;
    for (int j = i; j < NN; j += stride) g_deg[j] = 0;
    for (int j = i; j < GG * CC; j += stride) g_pool[j] = 0.f;
    for (int j = i; j < GG; j += stride) g_cnt[j] = 0;
}

// ---------------- CSR build: histogram ----------------
__global__ void k_hist(const int* __restrict__ ei) {
    int t = blockIdx.x * blockDim.x + threadIdx.x;
    if (t < EE) atomicAdd(&g_deg[ei[EE + t]], 1);
}

// ---------------- CSR build: single-block exclusive scan over 50k counts -----
__global__ __launch_bounds__(1024) void k_scan() {
    __shared__ int warpsum[32];
    const int t = threadIdx.x;
    const int per = (NN + 1023) / 1024;   // 49
    const int base = t * per;
    int sum = 0;
    for (int i = 0; i < per; i++) {
        int idx = base + i;
        if (idx < NN) sum += g_deg[idx];
    }
    const int lane = t & 31, wid = t >> 5;
    int v = sum;
#pragma unroll
    for (int off = 1; off < 32; off <<= 1) {
        int u = __shfl_up_sync(0xffffffffu, v, off);
        if (lane >= off) v += u;
    }
    if (lane == 31) warpsum[wid] = v;
    __syncthreads();
    if (wid == 0) {
        int wv = warpsum[lane];
#pragma unroll
        for (int off = 1; off < 32; off <<= 1) {
            int u = __shfl_up_sync(0xffffffffu, wv, off);
            if (lane >= off) wv += u;
        }
        warpsum[lane] = wv;
    }
    __syncthreads();
    int excl = v - sum + (wid > 0 ? warpsum[wid - 1] : 0);
    int run = excl;
    for (int i = 0; i < per; i++) {
        int idx = base + i;
        if (idx < NN) {
            int c = g_deg[idx];
            g_off[idx] = run;
            g_woff[idx] = run;
            run += c;
        }
    }
    if (t == 1023) g_off[NN] = run;
}

// ---------------- CSR build: scatter src ids ----------------
__global__ void k_scatter(const int* __restrict__ ei) {
    int t = blockIdx.x * blockDim.x + threadIdx.x;
    if (t < EE) {
        int dst = ei[EE + t];
        int pos = atomicAdd(&g_woff[dst], 1);
        g_csrc[pos] = ei[t];
    }
}

// ---------------- K1: xl = x@Wl+bl, xr = x@Wr+br (blockIdx.z selects) ----------
// BM=BN=128, BK=16, 256 threads, 8x8 microtile, FFMA2 inner loop, fp16 output.
__global__ __launch_bounds__(256) void k_gemm(const float* __restrict__ x,
                                              const float* __restrict__ Wl,
                                              const float* __restrict__ bl,
                                              const float* __restrict__ Wr,
                                              const float* __restrict__ br) {
    const float* W    = blockIdx.z ? Wr : Wl;
    const float* bias = blockIdx.z ? br : bl;
    __half* out       = blockIdx.z ? g_xr : g_xl;

    __shared__ unsigned long long As2[16][128]; // a duplicated-packed: 16 KB
    __shared__ float Bs[16][128];               // 8 KB

    const int tid = threadIdx.x;
    const int tx = tid & 15, ty = tid >> 4;
    const int bm = blockIdx.x * 128, bn = blockIdx.y * 128;

    unsigned long long acc[8][4];
#pragma unroll
    for (int r = 0; r < 8; r++)
#pragma unroll
        for (int p = 0; p < 4; p++) acc[r][p] = 0ull;

    const int arow = tid >> 2;         // 0..63
    const int acol = (tid & 3) << 2;   // 0,4,8,12
    const int brow = tid >> 5;         // 0..7
    const int bcol = (tid & 31) << 2;  // 0..124

    for (int k0 = 0; k0 < DIN_; k0 += 16) {
#pragma unroll
        for (int rr = 0; rr < 2; rr++) {
            int r = arow + rr * 64;
            int gm = bm + r;
            float4 v = make_float4(0.f, 0.f, 0.f, 0.f);
            if (gm < NN) v = *(const float4*)&x[gm * DIN_ + k0 + acol];
            As2[acol + 0][r] = pack2(v.x, v.x);
            As2[acol + 1][r] = pack2(v.y, v.y);
            As2[acol + 2][r] = pack2(v.z, v.z);
            As2[acol + 3][r] = pack2(v.w, v.w);
        }
#pragma unroll
        for (int rr = 0; rr < 2; rr++) {
            int r = brow + rr * 8;
            *(float4*)&Bs[r][bcol] = *(const float4*)&W[(k0 + r) * HC + bn + bcol];
        }
        __syncthreads();
#pragma unroll
        for (int kk = 0; kk < 16; kk++) {
            ulonglong2 a01 = *(const ulonglong2*)&As2[kk][ty * 8 + 0];
            ulonglong2 a23 = *(const ulonglong2*)&As2[kk][ty * 8 + 2];
            ulonglong2 a45 = *(const ulonglong2*)&As2[kk][ty * 8 + 4];
            ulonglong2 a67 = *(const ulonglong2*)&As2[kk][ty * 8 + 6];
            ulonglong2 b01 = *(const ulonglong2*)&Bs[kk][tx * 8 + 0];
            ulonglong2 b23 = *(const ulonglong2*)&Bs[kk][tx * 8 + 4];
            unsigned long long av[8] = {a01.x, a01.y, a23.x, a23.y,
                                        a45.x, a45.y, a67.x, a67.y};
            unsigned long long bv[4] = {b01.x, b01.y, b23.x, b23.y};
#pragma unroll
            for (int r = 0; r < 8; r++) {
#pragma unroll
                for (int p = 0; p < 4; p++) acc[r][p] = fma2(av[r], bv[p], acc[r][p]);
            }
        }
        __syncthreads();
    }

    float bvals[8];
#pragma unroll
    for (int j = 0; j < 8; j++) bvals[j] = bias[bn + tx * 8 + j];
#pragma unroll
    for (int r = 0; r < 8; r++) {
        int gm = bm + ty * 8 + r;
        if (gm < NN) {
            float o[8];
#pragma unroll
            for (int p = 0; p < 4; p++) unpack2(acc[r][p], o[2 * p], o[2 * p + 1]);
#pragma unroll
            for (int j = 0; j < 8; j++) o[j] += bvals[j];
            __half2 h[4];
#pragma unroll
            for (int p = 0; p < 4; p++)
                h[p] = __floats2half2_rn(o[2 * p], o[2 * p + 1]);
            *(uint4*)&out[gm * HC + bn + tx * 8] = *(uint4*)h;
        }
    }
}

// ---------------- K2: fused node-centric attention + aggregate + pool ----------
// One warp per dst node. Lane l covers flat elements [8l, 8l+8) of the H*C row
// (head = l>>3, channels (l&7)*8 .. +8 of that head). fp16 gathers, fp32 math.
// Softmax without max-shift (logits are O(10), exp safe; shift-invariant math).
__global__ __launch_bounds__(256) void k_node(const float* __restrict__ att,
                                              const float* __restrict__ bgnn,
                                              const int* __restrict__ batch) {
    const int lane = threadIdx.x & 31;
    int w = (blockIdx.x * blockDim.x + threadIdx.x) >> 5;
    const int nw = (gridDim.x * blockDim.x) >> 5;

    const float4 at0 = *(const float4*)&att[lane * 8 + 0];
    const float4 at1 = *(const float4*)&att[lane * 8 + 4];

    for (int n = w; n < NN; n += nw) {
        // load xr row slice (8 halves = 16B) and convert to fp32
        uint4 ur = *(const uint4*)&g_xr[n * HC + lane * 8];
        const float2 r0 = __half22float2(*(__half2*)&ur.x);
        const float2 r1 = __half22float2(*(__half2*)&ur.y);
        const float2 r2 = __half22float2(*(__half2*)&ur.z);
        const float2 r3 = __half22float2(*(__half2*)&ur.w);

        float acc[8];
#pragma unroll
        for (int j = 0; j < 8; j++) acc[j] = 0.f;
        float D = 0.f;

        const int beg = g_off[n], end = g_off[n + 1];
        // e == beg-1 encodes the self loop (src = n); then the CSR entries.
        for (int e = beg - 1; e < end; e++) {
            const int src = (e < beg) ? n : g_csrc[e];
            uint4 ul = *(const uint4*)&g_xl[src * HC + lane * 8];
            const float2 l0 = __half22float2(*(__half2*)&ul.x);
            const float2 l1 = __half22float2(*(__half2*)&ul.y);
            const float2 l2 = __half22float2(*(__half2*)&ul.z);
            const float2 l3 = __half22float2(*(__half2*)&ul.w);

            float p = 0.f, z;
            z = l0.x + r0.x; p = fmaf(fmaf(0.8f, fmaxf(z, 0.f), 0.2f * z), at0.x, p);
            z = l0.y + r0.y; p = fmaf(fmaf(0.8f, fmaxf(z, 0.f), 0.2f * z), at0.y, p);
            z = l1.x + r1.x; p = fmaf(fmaf(0.8f, fmaxf(z, 0.f), 0.2f * z), at0.z, p);
            z = l1.y + r1.y; p = fmaf(fmaf(0.8f, fmaxf(z, 0.f), 0.2f * z), at0.w, p);
            z = l2.x + r2.x; p = fmaf(fmaf(0.8f, fmaxf(z, 0.f), 0.2f * z), at1.x, p);
            z = l2.y + r2.y; p = fmaf(fmaf(0.8f, fmaxf(z, 0.f), 0.2f * z), at1.y, p);
            z = l3.x + r3.x; p = fmaf(fmaf(0.8f, fmaxf(z, 0.f), 0.2f * z), at1.z, p);
            z = l3.y + r3.y; p = fmaf(fmaf(0.8f, fmaxf(z, 0.f), 0.2f * z), at1.w, p);

            // sum within each 8-lane head group; every lane ends with head sum
            p += __shfl_xor_sync(0xffffffffu, p, 4);
            p += __shfl_xor_sync(0xffffffffu, p, 2);
            p += __shfl_xor_sync(0xffffffffu, p, 1);

            const float a = __expf(p);
            D += a;
            acc[0] = fmaf(a, l0.x, acc[0]);
            acc[1] = fmaf(a, l0.y, acc[1]);
            acc[2] = fmaf(a, l1.x, acc[2]);
            acc[3] = fmaf(a, l1.y, acc[3]);
            acc[4] = fmaf(a, l2.x, acc[4]);
            acc[5] = fmaf(a, l2.y, acc[5]);
            acc[6] = fmaf(a, l3.x, acc[6]);
            acc[7] = fmaf(a, l3.y, acc[7]);
        }

        // normalize per head, then mean across heads (lanes {l, l^8, l^16, l^24})
        const float inv = 1.f / (D + 1e-16f);
        float v[8];
#pragma unroll
        for (int j = 0; j < 8; j++) {
            float t = acc[j] * inv;
            t += __shfl_xor_sync(0xffffffffu, t, 8);
            t += __shfl_xor_sync(0xffffffffu, t, 16);
            v[j] = t;
        }

        if (lane < 8) {
            const int g = batch[n];
            if (lane == 0) atomicAdd(&g_cnt[g], 1);
#pragma unroll
            for (int j = 0; j < 8; j++) {
                const int c = lane * 8 + j;
                float val = 0.25f * v[j] + bgnn[c];
                val = val > 0.f ? val : 0.01f * val;   // outer leaky_relu(0.01)
                atomicAdd(&g_pool[g * CC + c], val);
            }
        }
    }
}

// ---------------- K3: final FC  out[g, :] = [hy[g], hg[g]] @ Wfc + bfc ----------
__global__ __launch_bounds__(256) void k_fc(const float* __restrict__ hy,
                                            const float* __restrict__ Wfc,
                                            const float* __restrict__ bfc,
                                            float* __restrict__ out) {
    const int g = blockIdx.x;
    const int j = threadIdx.x;
    __shared__ float sh[DENC_ + CC];
    sh[j] = hy[g * DENC_ + j];
    if (j < CC) {
        int c = g_cnt[g];
        float cn = c > 0 ? (float)c : 1.f;
        sh[DENC_ + j] = g_pool[g * CC + j] / cn;
    }
    __syncthreads();
    float acc = bfc[j];
#pragma unroll 8
    for (int k = 0; k < DENC_ + CC; k++)
        acc = fmaf(sh[k], Wfc[k * DENC_ + j], acc);
    out[g * DENC_ + j] = acc;
}

// ---------------- launch ----------------
extern "C" void kernel_launch(void* const* d_in, const int* in_sizes, int n_in,
                              void* d_out, int out_size) {
    const float* hy   = (const float*)d_in[0];
    const float* x    = (const float*)d_in[1];
    const int*   ei   = (const int*)d_in[2];
    const int*   batch= (const int*)d_in[3];
    const float* Wl   = (const float*)d_in[4];
    const float* bl   = (const float*)d_in[5];
    const float* Wr   = (const float*)d_in[6];
    const float* br   = (const float*)d_in[7];
    const float* att  = (const float*)d_in[8];
    const float* bgnn = (const float*)d_in[9];
    const float* Wfc  = (const float*)d_in[10];
    const float* bfc  = (const float*)d_in[11];
    float* out = (float*)d_out;

    k_init<<<256, 256>>>();
    k_hist<<<(EE + 255) / 256, 256>>>(ei);
    k_scan<<<1, 1024>>>();
    k_scatter<<<(EE + 255) / 256, 256>>>(ei);
    k_gemm<<<dim3((NN + 127) / 128, HC / 128, 2), 256>>>(x, Wl, bl, Wr, br);
    k_node<<<(NN / 8) + 1, 256>>>(att, bgnn, batch);
    k_fc<<<GG, 256>>>(hy, Wfc, bfc, out);
}

// round 4
// speedup vs baseline: 1.7212x; 1.4633x over previous
#include <cuda_runtime.h>
#include <cuda_fp16.h>
#include <math.h>
#include <limits.h>

#define NN   50000
#define EE   800000
#define GG   512
#define HH   4
#define CC   64
#define HC   256      // H*C
#define DIN_ 128
#define DENC_ 256

// ---------------- scratch (static device arrays; no allocation) ----------------
__device__ __half g_xl[NN * HC];     // 25.6 MB (fp16 node features, source)
__device__ __half g_xr[NN * HC];     // 25.6 MB (fp16 node features, target)
__device__ __half g_xh[NN * DIN_];   // 12.8 MB (fp16 input features)
__device__ __half g_whl[DIN_ * HC];  // fp16 weights
__device__ __half g_whr[DIN_ * HC];
__device__ int   g_deg[NN];          // in-degree histogram (real edges only)
__device__ int   g_off[NN + 1];      // CSR row offsets
__device__ int   g_woff[NN];         // working copy for scatter
__device__ int   g_csrc[EE];         // CSR: src node per incoming edge
__device__ float g_pool[GG * CC];    // per-graph sums
__device__ int   g_cnt[GG];          // per-graph node counts

// ---------------- mma helpers ----------------
__device__ __forceinline__ unsigned smem_u32(const void* p) {
    return (unsigned)__cvta_generic_to_shared(p);
}
__device__ __forceinline__ void ldm_x4(unsigned& r0, unsigned& r1, unsigned& r2,
                                       unsigned& r3, unsigned addr) {
    asm volatile("ldmatrix.sync.aligned.m8n8.x4.shared.b16 {%0,%1,%2,%3}, [%4];"
                 : "=r"(r0), "=r"(r1), "=r"(r2), "=r"(r3) : "r"(addr));
}
__device__ __forceinline__ void ldm_x4_t(unsigned& r0, unsigned& r1, unsigned& r2,
                                         unsigned& r3, unsigned addr) {
    asm volatile("ldmatrix.sync.aligned.m8n8.x4.trans.shared.b16 {%0,%1,%2,%3}, [%4];"
                 : "=r"(r0), "=r"(r1), "=r"(r2), "=r"(r3) : "r"(addr));
}
__device__ __forceinline__ void mma16816(float* d, const unsigned* a, const unsigned* b) {
    asm volatile(
        "mma.sync.aligned.m16n8k16.row.col.f32.f16.f16.f32 "
        "{%0,%1,%2,%3}, {%4,%5,%6,%7}, {%8,%9}, {%0,%1,%2,%3};"
        : "+f"(d[0]), "+f"(d[1]), "+f"(d[2]), "+f"(d[3])
        : "r"(a[0]), "r"(a[1]), "r"(a[2]), "r"(a[3]), "r"(b[0]), "r"(b[1]));
}

// ---------------- K1: convert inputs to fp16 + zero scratch ----------------
__global__ void k_cvt(const float* __restrict__ x,
                      const float* __restrict__ Wl,
                      const float* __restrict__ Wr) {
    int i = blockIdx.x * blockDim.x + threadIdx.x;
    int stride = gridDim.x * blockDim.x;
    for (int j = i; j < NN * DIN_ / 2; j += stride) {
        float2 v = ((const float2*)x)[j];
        ((__half2*)g_xh)[j] = __floats2half2_rn(v.x, v.y);
    }
    for (int j = i; j < DIN_ * HC / 2; j += stride) {
        float2 a = ((const float2*)Wl)[j];
        float2 b = ((const float2*)Wr)[j];
        ((__half2*)g_whl)[j] = __floats2half2_rn(a.x, a.y);
        ((__half2*)g_whr)[j] = __floats2half2_rn(b.x, b.y);
    }
    for (int j = i; j < NN; j += stride) g_deg[j] = 0;
    for (int j = i; j < GG * CC; j += stride) g_pool[j] = 0.f;
    for (int j = i; j < GG; j += stride) g_cnt[j] = 0;
}

// ---------------- CSR build: histogram ----------------
__global__ void k_hist(const int* __restrict__ ei) {
    int t = blockIdx.x * blockDim.x + threadIdx.x;
    if (t < EE) atomicAdd(&g_deg[ei[EE + t]], 1);
}

// ---------------- CSR build: single-block exclusive scan over 50k counts -----
__global__ __launch_bounds__(1024) void k_scan() {
    __shared__ int warpsum[32];
    const int t = threadIdx.x;
    const int per = (NN + 1023) / 1024;   // 49
    const int base = t * per;
    int sum = 0;
    for (int i = 0; i < per; i++) {
        int idx = base + i;
        if (idx < NN) sum += g_deg[idx];
    }
    const int lane = t & 31, wid = t >> 5;
    int v = sum;
#pragma unroll
    for (int off = 1; off < 32; off <<= 1) {
        int u = __shfl_up_sync(0xffffffffu, v, off);
        if (lane >= off) v += u;
    }
    if (lane == 31) warpsum[wid] = v;
    __syncthreads();
    if (wid == 0) {
        int wv = warpsum[lane];
#pragma unroll
        for (int off = 1; off < 32; off <<= 1) {
            int u = __shfl_up_sync(0xffffffffu, wv, off);
            if (lane >= off) wv += u;
        }
        warpsum[lane] = wv;
    }
    __syncthreads();
    int excl = v - sum + (wid > 0 ? warpsum[wid - 1] : 0);
    int run = excl;
    for (int i = 0; i < per; i++) {
        int idx = base + i;
        if (idx < NN) {
            int c = g_deg[idx];
            g_off[idx] = run;
            g_woff[idx] = run;
            run += c;
        }
    }
    if (t == 1023) g_off[NN] = run;
}

// ---------------- K-GEMM: tensor-core xl = x@Wl+bl, xr = x@Wr+br ----------------
// BM=128, BN=64, full K=128 resident. 8 warps as 4(m)x2(n), warp tile 32x32.
// XOR-swizzled smem + ldmatrix, mma.m16n8k16 f16->f32, fp16 output.
__global__ __launch_bounds__(256) void k_gemm(const float* __restrict__ bl,
                                              const float* __restrict__ br) {
    __shared__ __half sA[128 * 128];  // 32 KB
    __shared__ __half sB[128 * 64];   // 16 KB

    const __half* W   = blockIdx.z ? g_whr : g_whl;
    const float* bias = blockIdx.z ? br : bl;
    __half* out       = blockIdx.z ? g_xr : g_xl;

    const int tid = threadIdx.x;
    const int bm = blockIdx.x * 128, bn = blockIdx.y * 64;

    // load A tile (128 rows x 128 halves; 16B chunks, chunk' = chunk ^ (row&7))
#pragma unroll
    for (int it = 0; it < 8; it++) {
        int q = it * 256 + tid;
        int row = q >> 4, cc = q & 15;
        int gm = bm + row;
        uint4 v = make_uint4(0u, 0u, 0u, 0u);
        if (gm < NN) v = *(const uint4*)&g_xh[gm * DIN_ + cc * 8];
        *(uint4*)&sA[row * 128 + ((cc ^ (row & 7)) << 3)] = v;
    }
    // load B tile (128 rows x 64 halves; 8 chunks/row)
#pragma unroll
    for (int it = 0; it < 4; it++) {
        int q = it * 256 + tid;
        int row = q >> 3, cc = q & 7;
        uint4 v = *(const uint4*)&W[row * HC + bn + cc * 8];
        *(uint4*)&sB[row * 64 + ((cc ^ (row & 7)) << 3)] = v;
    }
    __syncthreads();

    const int wid = tid >> 5, lane = tid & 31;
    const int wm = (wid & 3) * 32;   // warp m offset in tile
    const int wn = (wid >> 2) * 32;  // warp n offset in tile

    float acc[2][4][4];
#pragma unroll
    for (int i = 0; i < 2; i++)
#pragma unroll
        for (int j = 0; j < 4; j++)
#pragma unroll
            for (int k = 0; k < 4; k++) acc[i][j][k] = 0.f;

#pragma unroll
    for (int ks = 0; ks < 8; ks++) {
        const int k0 = ks * 16;
        unsigned a[2][4], b[4][2];
#pragma unroll
        for (int am = 0; am < 2; am++) {
            int row = wm + am * 16 + (lane & 15);
            int cc = (k0 >> 3) + (lane >> 4);
            unsigned addr = smem_u32(&sA[row * 128 + ((cc ^ (row & 7)) << 3)]);
            ldm_x4(a[am][0], a[am][1], a[am][2], a[am][3], addr);
        }
#pragma unroll
        for (int bt = 0; bt < 2; bt++) {
            int row = k0 + (lane & 15);
            int cc = ((wn + bt * 16) >> 3) + (lane >> 4);
            unsigned addr = smem_u32(&sB[row * 64 + ((cc ^ (row & 7)) << 3)]);
            unsigned r0, r1, r2, r3;
            ldm_x4_t(r0, r1, r2, r3, addr);
            b[bt * 2 + 0][0] = r0; b[bt * 2 + 0][1] = r1;
            b[bt * 2 + 1][0] = r2; b[bt * 2 + 1][1] = r3;
        }
#pragma unroll
        for (int am = 0; am < 2; am++)
#pragma unroll
            for (int bt = 0; bt < 4; bt++) mma16816(acc[am][bt], a[am], b[bt]);
    }

    // epilogue: + bias, fp16 store
#pragma unroll
    for (int am = 0; am < 2; am++) {
        int row0 = bm + wm + am * 16 + (lane >> 2);
#pragma unroll
        for (int bt = 0; bt < 4; bt++) {
            int col = bn + wn + bt * 8 + (lane & 3) * 2;
            float b0 = bias[col], b1 = bias[col + 1];
            if (row0 < NN)
                *(__half2*)&out[row0 * HC + col] =
                    __floats2half2_rn(acc[am][bt][0] + b0, acc[am][bt][1] + b1);
            if (row0 + 8 < NN)
                *(__half2*)&out[(row0 + 8) * HC + col] =
                    __floats2half2_rn(acc[am][bt][2] + b0, acc[am][bt][3] + b1);
        }
    }
}

// ---------------- CSR build: scatter src ids ----------------
__global__ void k_scatter(const int* __restrict__ ei) {
    int t = blockIdx.x * blockDim.x + threadIdx.x;
    if (t < EE) {
        int dst = ei[EE + t];
        int pos = atomicAdd(&g_woff[dst], 1);
        g_csrc[pos] = ei[t];
    }
}

// ---------------- K-NODE: fused node-centric attention + aggregate + pool ------
__global__ __launch_bounds__(256) void k_node(const float* __restrict__ att,
                                              const float* __restrict__ bgnn,
                                              const int* __restrict__ batch) {
    const int lane = threadIdx.x & 31;
    int w = (blockIdx.x * blockDim.x + threadIdx.x) >> 5;
    const int nw = (gridDim.x * blockDim.x) >> 5;

    const float4 at0 = *(const float4*)&att[lane * 8 + 0];
    const float4 at1 = *(const float4*)&att[lane * 8 + 4];

    for (int n = w; n < NN; n += nw) {
        uint4 ur = *(const uint4*)&g_xr[n * HC + lane * 8];
        const float2 r0 = __half22float2(*(__half2*)&ur.x);
        const float2 r1 = __half22float2(*(__half2*)&ur.y);
        const float2 r2 = __half22float2(*(__half2*)&ur.z);
        const float2 r3 = __half22float2(*(__half2*)&ur.w);

        float acc[8];
#pragma unroll
        for (int j = 0; j < 8; j++) acc[j] = 0.f;
        float D = 0.f;

        const int beg = g_off[n], end = g_off[n + 1];
        for (int e = beg - 1; e < end; e++) {
            const int src = (e < beg) ? n : g_csrc[e];
            uint4 ul = *(const uint4*)&g_xl[src * HC + lane * 8];
            const float2 l0 = __half22float2(*(__half2*)&ul.x);
            const float2 l1 = __half22float2(*(__half2*)&ul.y);
            const float2 l2 = __half22float2(*(__half2*)&ul.z);
            const float2 l3 = __half22float2(*(__half2*)&ul.w);

            float p = 0.f, z;
            z = l0.x + r0.x; p = fmaf(fmaf(0.8f, fmaxf(z, 0.f), 0.2f * z), at0.x, p);
            z = l0.y + r0.y; p = fmaf(fmaf(0.8f, fmaxf(z, 0.f), 0.2f * z), at0.y, p);
            z = l1.x + r1.x; p = fmaf(fmaf(0.8f, fmaxf(z, 0.f), 0.2f * z), at0.z, p);
            z = l1.y + r1.y; p = fmaf(fmaf(0.8f, fmaxf(z, 0.f), 0.2f * z), at0.w, p);
            z = l2.x + r2.x; p = fmaf(fmaf(0.8f, fmaxf(z, 0.f), 0.2f * z), at1.x, p);
            z = l2.y + r2.y; p = fmaf(fmaf(0.8f, fmaxf(z, 0.f), 0.2f * z), at1.y, p);
            z = l3.x + r3.x; p = fmaf(fmaf(0.8f, fmaxf(z, 0.f), 0.2f * z), at1.z, p);
            z = l3.y + r3.y; p = fmaf(fmaf(0.8f, fmaxf(z, 0.f), 0.2f * z), at1.w, p);

            p += __shfl_xor_sync(0xffffffffu, p, 4);
            p += __shfl_xor_sync(0xffffffffu, p, 2);
            p += __shfl_xor_sync(0xffffffffu, p, 1);

            const float a = __expf(p);
            D += a;
            acc[0] = fmaf(a, l0.x, acc[0]);
            acc[1] = fmaf(a, l0.y, acc[1]);
            acc[2] = fmaf(a, l1.x, acc[2]);
            acc[3] = fmaf(a, l1.y, acc[3]);
            acc[4] = fmaf(a, l2.x, acc[4]);
            acc[5] = fmaf(a, l2.y, acc[5]);
            acc[6] = fmaf(a, l3.x, acc[6]);
            acc[7] = fmaf(a, l3.y, acc[7]);
        }

        const float inv = 1.f / (D + 1e-16f);
        float v[8];
#pragma unroll
        for (int j = 0; j < 8; j++) {
            float t = acc[j] * inv;
            t += __shfl_xor_sync(0xffffffffu, t, 8);
            t += __shfl_xor_sync(0xffffffffu, t, 16);
            v[j] = t;
        }

        if (lane < 8) {
            const int g = batch[n];
            if (lane == 0) atomicAdd(&g_cnt[g], 1);
#pragma unroll
            for (int j = 0; j < 8; j++) {
                const int c = lane * 8 + j;
                float val = 0.25f * v[j] + bgnn[c];
                val = val > 0.f ? val : 0.01f * val;
                atomicAdd(&g_pool[g * CC + c], val);
            }
        }
    }
}

// ---------------- K-FC: out[g, :] = [hy[g], hg[g]] @ Wfc + bfc ----------------
__global__ __launch_bounds__(256) void k_fc(const float* __restrict__ hy,
                                            const float* __restrict__ Wfc,
                                            const float* __restrict__ bfc,
                                            float* __restrict__ out) {
    const int g = blockIdx.x;
    const int j = threadIdx.x;
    __shared__ float sh[DENC_ + CC];
    sh[j] = hy[g * DENC_ + j];
    if (j < CC) {
        int c = g_cnt[g];
        float cn = c > 0 ? (float)c : 1.f;
        sh[DENC_ + j] = g_pool[g * CC + j] / cn;
    }
    __syncthreads();
    float acc = bfc[j];
#pragma unroll 8
    for (int k = 0; k < DENC_ + CC; k++)
        acc = fmaf(sh[k], Wfc[k * DENC_ + j], acc);
    out[g * DENC_ + j] = acc;
}

// ---------------- launch ----------------
extern "C" void kernel_launch(void* const* d_in, const int* in_sizes, int n_in,
                              void* d_out, int out_size) {
    const float* hy   = (const float*)d_in[0];
    const float* x    = (const float*)d_in[1];
    const int*   ei   = (const int*)d_in[2];
    const int*   batch= (const int*)d_in[3];
    const float* Wl   = (const float*)d_in[4];
    const float* bl   = (const float*)d_in[5];
    const float* Wr   = (const float*)d_in[6];
    const float* br   = (const float*)d_in[7];
    const float* att  = (const float*)d_in[8];
    const float* bgnn = (const float*)d_in[9];
    const float* Wfc  = (const float*)d_in[10];
    const float* bfc  = (const float*)d_in[11];
    float* out = (float*)d_out;

    k_cvt<<<512, 256>>>(x, Wl, Wr);                       // #1
    k_hist<<<(EE + 255) / 256, 256>>>(ei);                // #2
    k_scan<<<1, 1024>>>();                                // #3
    k_gemm<<<dim3((NN + 127) / 128, HC / 64, 2), 256>>>(bl, br);  // #4 (profiled slot)
    k_scatter<<<(EE + 255) / 256, 256>>>(ei);             // #5
    k_node<<<(NN / 8) + 1, 256>>>(att, bgnn, batch);      // #6
    k_fc<<<GG, 256>>>(hy, Wfc, bfc, out);                 // #7
}

// round 5
// speedup vs baseline: 1.8349x; 1.0661x over previous
#include <cuda_runtime.h>
#include <cuda_fp16.h>
#include <math.h>
#include <limits.h>

#define NN   50000
#define EE   800000
#define GG   512
#define HH   4
#define CC   64
#define HC   256      // H*C
#define DIN_ 128
#define DENC_ 256

#define MTILES 391          // (NN+127)/128
#define SCAT_BLOCKS 3125    // (EE+255)/256
#define GEMM_BLOCKS (MTILES * 4 * 2)

// ---------------- scratch (static device arrays; no allocation) ----------------
__device__ __half g_xl[NN * HC];     // 25.6 MB (fp16 node features, source)
__device__ __half g_xr[NN * HC];     // 25.6 MB (fp16 node features, target)
__device__ __half g_xh[NN * DIN_];   // 12.8 MB (fp16 input features)
__device__ __half g_whl[DIN_ * HC];  // fp16 weights
__device__ __half g_whr[DIN_ * HC];
__device__ int   g_deg[NN];          // in-degree histogram (real edges only)
__device__ int   g_off[NN + 1];      // CSR row offsets
__device__ int   g_woff[NN];         // working copy for scatter
__device__ int   g_csrc[EE];         // CSR: src node per incoming edge
__device__ float g_pool[GG * CC];    // per-graph sums
__device__ int   g_cnt[GG];          // per-graph node counts

// ---------------- mma helpers ----------------
__device__ __forceinline__ unsigned smem_u32(const void* p) {
    return (unsigned)__cvta_generic_to_shared(p);
}
__device__ __forceinline__ void ldm_x4(unsigned& r0, unsigned& r1, unsigned& r2,
                                       unsigned& r3, unsigned addr) {
    asm volatile("ldmatrix.sync.aligned.m8n8.x4.shared.b16 {%0,%1,%2,%3}, [%4];"
                 : "=r"(r0), "=r"(r1), "=r"(r2), "=r"(r3) : "r"(addr));
}
__device__ __forceinline__ void ldm_x4_t(unsigned& r0, unsigned& r1, unsigned& r2,
                                         unsigned& r3, unsigned addr) {
    asm volatile("ldmatrix.sync.aligned.m8n8.x4.trans.shared.b16 {%0,%1,%2,%3}, [%4];"
                 : "=r"(r0), "=r"(r1), "=r"(r2), "=r"(r3) : "r"(addr));
}
__device__ __forceinline__ void mma16816(float* d, const unsigned* a, const unsigned* b) {
    asm volatile(
        "mma.sync.aligned.m16n8k16.row.col.f32.f16.f16.f32 "
        "{%0,%1,%2,%3}, {%4,%5,%6,%7}, {%8,%9}, {%0,%1,%2,%3};"
        : "+f"(d[0]), "+f"(d[1]), "+f"(d[2]), "+f"(d[3])
        : "r"(a[0]), "r"(a[1]), "r"(a[2]), "r"(a[3]), "r"(b[0]), "r"(b[1]));
}

// ---------------- K1: convert to fp16 + degree histogram + zero scratch --------
__global__ void k_cvt(const float* __restrict__ x,
                      const float* __restrict__ Wl,
                      const float* __restrict__ Wr,
                      const int* __restrict__ ei) {
    int i = blockIdx.x * blockDim.x + threadIdx.x;
    int stride = gridDim.x * blockDim.x;
    for (int j = i; j < NN; j += stride) g_deg[j] = 0;
    for (int j = i; j < GG * CC; j += stride) g_pool[j] = 0.f;
    for (int j = i; j < GG; j += stride) g_cnt[j] = 0;
    for (int j = i; j < NN * DIN_ / 2; j += stride) {
        float2 v = ((const float2*)x)[j];
        ((__half2*)g_xh)[j] = __floats2half2_rn(v.x, v.y);
    }
    for (int j = i; j < DIN_ * HC / 2; j += stride) {
        float2 a = ((const float2*)Wl)[j];
        float2 b = ((const float2*)Wr)[j];
        ((__half2*)g_whl)[j] = __floats2half2_rn(a.x, a.y);
        ((__half2*)g_whr)[j] = __floats2half2_rn(b.x, b.y);
    }
    // needs g_deg zeroed: done by THIS kernel before grid-wide reconvergence?
    // No — grid-stride zero above is not globally ordered vs. the atomics below.
    // Safe because each thread zeroes its own j-range BEFORE any atomics only
    // within the thread; cross-thread order is not guaranteed. So do the
    // histogram in a separate grid-stride pass gated per-element is unsafe.
    // => histogram moved to k_hist_phase below via second launch param trick.
}

// histogram as its own kernel (needs g_deg fully zeroed first)
__global__ void k_hist(const int* __restrict__ ei) {
    int t = blockIdx.x * blockDim.x + threadIdx.x;
    if (t < EE) atomicAdd(&g_deg[ei[EE + t]], 1);
}

// ---------------- CSR build: single-block exclusive scan over 50k counts -----
__global__ __launch_bounds__(1024) void k_scan() {
    __shared__ int warpsum[32];
    const int t = threadIdx.x;
    const int per = (NN + 1023) / 1024;   // 49
    const int base = t * per;
    int sum = 0;
    for (int i = 0; i < per; i++) {
        int idx = base + i;
        if (idx < NN) sum += g_deg[idx];
    }
    const int lane = t & 31, wid = t >> 5;
    int v = sum;
#pragma unroll
    for (int off = 1; off < 32; off <<= 1) {
        int u = __shfl_up_sync(0xffffffffu, v, off);
        if (lane >= off) v += u;
    }
    if (lane == 31) warpsum[wid] = v;
    __syncthreads();
    if (wid == 0) {
        int wv = warpsum[lane];
#pragma unroll
        for (int off = 1; off < 32; off <<= 1) {
            int u = __shfl_up_sync(0xffffffffu, wv, off);
            if (lane >= off) wv += u;
        }
        warpsum[lane] = wv;
    }
    __syncthreads();
    int excl = v - sum + (wid > 0 ? warpsum[wid - 1] : 0);
    int run = excl;
    for (int i = 0; i < per; i++) {
        int idx = base + i;
        if (idx < NN) {
            int c = g_deg[idx];
            g_off[idx] = run;
            g_woff[idx] = run;
            run += c;
        }
    }
    if (t == 1023) g_off[NN] = run;
}

// ---------------- K-MID: fused CSR-scatter + tensor-core GEMM ----------------
// Blocks [0, SCAT_BLOCKS): scatter src ids into CSR.
// Blocks [SCAT_BLOCKS, +GEMM_BLOCKS): 128x64 HMMA tiles of xl/xr = x@W+b.
__global__ __launch_bounds__(256) void k_mid(const float* __restrict__ bl,
                                             const float* __restrict__ br,
                                             const int* __restrict__ ei) {
    __shared__ __half sA[128 * 128];  // 32 KB
    __shared__ __half sB[128 * 64];   // 16 KB

    const int tid = threadIdx.x;
    int fb = blockIdx.x;

    if (fb < SCAT_BLOCKS) {           // ---- scatter part ----
        int t = fb * 256 + tid;
        if (t < EE) {
            int dst = ei[EE + t];
            int pos = atomicAdd(&g_woff[dst], 1);
            g_csrc[pos] = ei[t];
        }
        return;
    }
    fb -= SCAT_BLOCKS;                // ---- gemm part ----
    const int mb = fb % MTILES;
    const int rest = fb / MTILES;
    const int nb = rest & 3;
    const int z = rest >> 2;

    const __half* W   = z ? g_whr : g_whl;
    const float* bias = z ? br : bl;
    __half* out       = z ? g_xr : g_xl;
    const int bm = mb * 128, bn = nb * 64;

#pragma unroll
    for (int it = 0; it < 8; it++) {
        int q = it * 256 + tid;
        int row = q >> 4, cc = q & 15;
        int gm = bm + row;
        uint4 v = make_uint4(0u, 0u, 0u, 0u);
        if (gm < NN) v = *(const uint4*)&g_xh[gm * DIN_ + cc * 8];
        *(uint4*)&sA[row * 128 + ((cc ^ (row & 7)) << 3)] = v;
    }
#pragma unroll
    for (int it = 0; it < 4; it++) {
        int q = it * 256 + tid;
        int row = q >> 3, cc = q & 7;
        uint4 v = *(const uint4*)&W[row * HC + bn + cc * 8];
        *(uint4*)&sB[row * 64 + ((cc ^ (row & 7)) << 3)] = v;
    }
    __syncthreads();

    const int wid = tid >> 5, lane = tid & 31;
    const int wm = (wid & 3) * 32;
    const int wn = (wid >> 2) * 32;

    float acc[2][4][4];
#pragma unroll
    for (int i = 0; i < 2; i++)
#pragma unroll
        for (int j = 0; j < 4; j++)
#pragma unroll
            for (int k = 0; k < 4; k++) acc[i][j][k] = 0.f;

#pragma unroll
    for (int ks = 0; ks < 8; ks++) {
        const int k0 = ks * 16;
        unsigned a[2][4], b[4][2];
#pragma unroll
        for (int am = 0; am < 2; am++) {
            int row = wm + am * 16 + (lane & 15);
            int cc = (k0 >> 3) + (lane >> 4);
            unsigned addr = smem_u32(&sA[row * 128 + ((cc ^ (row & 7)) << 3)]);
            ldm_x4(a[am][0], a[am][1], a[am][2], a[am][3], addr);
        }
#pragma unroll
        for (int bt = 0; bt < 2; bt++) {
            int row = k0 + (lane & 15);
            int cc = ((wn + bt * 16) >> 3) + (lane >> 4);
            unsigned addr = smem_u32(&sB[row * 64 + ((cc ^ (row & 7)) << 3)]);
            unsigned r0, r1, r2, r3;
            ldm_x4_t(r0, r1, r2, r3, addr);
            b[bt * 2 + 0][0] = r0; b[bt * 2 + 0][1] = r1;
            b[bt * 2 + 1][0] = r2; b[bt * 2 + 1][1] = r3;
        }
#pragma unroll
        for (int am = 0; am < 2; am++)
#pragma unroll
            for (int bt = 0; bt < 4; bt++) mma16816(acc[am][bt], a[am], b[bt]);
    }

#pragma unroll
    for (int am = 0; am < 2; am++) {
        int row0 = bm + wm + am * 16 + (lane >> 2);
#pragma unroll
        for (int bt = 0; bt < 4; bt++) {
            int col = bn + wn + bt * 8 + (lane & 3) * 2;
            float b0 = bias[col], b1 = bias[col + 1];
            if (row0 < NN)
                *(__half2*)&out[row0 * HC + col] =
                    __floats2half2_rn(acc[am][bt][0] + b0, acc[am][bt][1] + b1);
            if (row0 + 8 < NN)
                *(__half2*)&out[(row0 + 8) * HC + col] =
                    __floats2half2_rn(acc[am][bt][2] + b0, acc[am][bt][3] + b1);
        }
    }
}

// ---------------- K-NODE: fused attention + aggregate + pool (4x pipelined) ----
__global__ __launch_bounds__(256) void k_node(const float* __restrict__ att,
                                              const float* __restrict__ bgnn,
                                              const int* __restrict__ batch) {
    const int lane = threadIdx.x & 31;
    int w = (blockIdx.x * blockDim.x + threadIdx.x) >> 5;
    const int nw = (gridDim.x * blockDim.x) >> 5;

    const float4 at0 = *(const float4*)&att[lane * 8 + 0];
    const float4 at1 = *(const float4*)&att[lane * 8 + 4];

    for (int n = w; n < NN; n += nw) {
        uint4 ur = *(const uint4*)&g_xr[n * HC + lane * 8];
        const float2 r0 = __half22float2(*(__half2*)&ur.x);
        const float2 r1 = __half22float2(*(__half2*)&ur.y);
        const float2 r2 = __half22float2(*(__half2*)&ur.z);
        const float2 r3 = __half22float2(*(__half2*)&ur.w);

        float acc[8];
#pragma unroll
        for (int j = 0; j < 8; j++) acc[j] = 0.f;
        float D = 0.f;

        auto doedge = [&](uint4 ul) {
            const float2 l0 = __half22float2(*(__half2*)&ul.x);
            const float2 l1 = __half22float2(*(__half2*)&ul.y);
            const float2 l2 = __half22float2(*(__half2*)&ul.z);
            const float2 l3 = __half22float2(*(__half2*)&ul.w);
            float p = 0.f, z;
            z = l0.x + r0.x; p = fmaf(fmaf(0.8f, fmaxf(z, 0.f), 0.2f * z), at0.x, p);
            z = l0.y + r0.y; p = fmaf(fmaf(0.8f, fmaxf(z, 0.f), 0.2f * z), at0.y, p);
            z = l1.x + r1.x; p = fmaf(fmaf(0.8f, fmaxf(z, 0.f), 0.2f * z), at0.z, p);
            z = l1.y + r1.y; p = fmaf(fmaf(0.8f, fmaxf(z, 0.f), 0.2f * z), at0.w, p);
            z = l2.x + r2.x; p = fmaf(fmaf(0.8f, fmaxf(z, 0.f), 0.2f * z), at1.x, p);
            z = l2.y + r2.y; p = fmaf(fmaf(0.8f, fmaxf(z, 0.f), 0.2f * z), at1.y, p);
            z = l3.x + r3.x; p = fmaf(fmaf(0.8f, fmaxf(z, 0.f), 0.2f * z), at1.z, p);
            z = l3.y + r3.y; p = fmaf(fmaf(0.8f, fmaxf(z, 0.f), 0.2f * z), at1.w, p);
            p += __shfl_xor_sync(0xffffffffu, p, 4);
            p += __shfl_xor_sync(0xffffffffu, p, 2);
            p += __shfl_xor_sync(0xffffffffu, p, 1);
            const float a = __expf(p);
            D += a;
            acc[0] = fmaf(a, l0.x, acc[0]);
            acc[1] = fmaf(a, l0.y, acc[1]);
            acc[2] = fmaf(a, l1.x, acc[2]);
            acc[3] = fmaf(a, l1.y, acc[3]);
            acc[4] = fmaf(a, l2.x, acc[4]);
            acc[5] = fmaf(a, l2.y, acc[5]);
            acc[6] = fmaf(a, l3.x, acc[6]);
            acc[7] = fmaf(a, l3.y, acc[7]);
        };

        // self loop
        doedge(*(const uint4*)&g_xl[n * HC + lane * 8]);

        const int beg = g_off[n], end = g_off[n + 1];
        int e = beg;
        const int end4 = beg + ((end - beg) & ~3);
        for (; e < end4; e += 4) {
            // 4 independent gathers in flight (MLP=4)
            const int s0 = g_csrc[e], s1 = g_csrc[e + 1];
            const int s2 = g_csrc[e + 2], s3 = g_csrc[e + 3];
            uint4 u0 = *(const uint4*)&g_xl[s0 * HC + lane * 8];
            uint4 u1 = *(const uint4*)&g_xl[s1 * HC + lane * 8];
            uint4 u2 = *(const uint4*)&g_xl[s2 * HC + lane * 8];
            uint4 u3 = *(const uint4*)&g_xl[s3 * HC + lane * 8];
            doedge(u0); doedge(u1); doedge(u2); doedge(u3);
        }
        for (; e < end; e++) {
            const int s = g_csrc[e];
            doedge(*(const uint4*)&g_xl[s * HC + lane * 8]);
        }

        const float inv = 1.f / (D + 1e-16f);
        float v[8];
#pragma unroll
        for (int j = 0; j < 8; j++) {
            float t = acc[j] * inv;
            t += __shfl_xor_sync(0xffffffffu, t, 8);
            t += __shfl_xor_sync(0xffffffffu, t, 16);
            v[j] = t;
        }

        if (lane < 8) {
            const int g = batch[n];
            if (lane == 0) atomicAdd(&g_cnt[g], 1);
#pragma unroll
            for (int j = 0; j < 8; j++) {
                const int c = lane * 8 + j;
                float val = 0.25f * v[j] + bgnn[c];
                val = val > 0.f ? val : 0.01f * val;
                atomicAdd(&g_pool[g * CC + c], val);
            }
        }
    }
}

// ---------------- K-FC: out[g, :] = [hy[g], hg[g]] @ Wfc + bfc ----------------
__global__ __launch_bounds__(256) void k_fc(const float* __restrict__ hy,
                                            const float* __restrict__ Wfc,
                                            const float* __restrict__ bfc,
                                            float* __restrict__ out) {
    const int g = blockIdx.x;
    const int j = threadIdx.x;
    __shared__ float sh[DENC_ + CC];
    sh[j] = hy[g * DENC_ + j];
    if (j < CC) {
        int c = g_cnt[g];
        float cn = c > 0 ? (float)c : 1.f;
        sh[DENC_ + j] = g_pool[g * CC + j] / cn;
    }
    __syncthreads();
    float acc = bfc[j];
#pragma unroll 8
    for (int k = 0; k < DENC_ + CC; k++)
        acc = fmaf(sh[k], Wfc[k * DENC_ + j], acc);
    out[g * DENC_ + j] = acc;
}

// ---------------- launch ----------------
extern "C" void kernel_launch(void* const* d_in, const int* in_sizes, int n_in,
                              void* d_out, int out_size) {
    const float* hy   = (const float*)d_in[0];
    const float* x    = (const float*)d_in[1];
    const int*   ei   = (const int*)d_in[2];
    const int*   batch= (const int*)d_in[3];
    const float* Wl   = (const float*)d_in[4];
    const float* bl   = (const float*)d_in[5];
    const float* Wr   = (const float*)d_in[6];
    const float* br   = (const float*)d_in[7];
    const float* att  = (const float*)d_in[8];
    const float* bgnn = (const float*)d_in[9];
    const float* Wfc  = (const float*)d_in[10];
    const float* bfc  = (const float*)d_in[11];
    float* out = (float*)d_out;

    k_cvt<<<512, 256>>>(x, Wl, Wr, ei);                        // #1 cvt + zero
    k_hist<<<(EE + 255) / 256, 256>>>(ei);                     // #2
    k_scan<<<1, 1024>>>();                                     // #3
    k_mid<<<SCAT_BLOCKS + GEMM_BLOCKS, 256>>>(bl, br, ei);     // #4 scatter+gemm
    k_node<<<(NN / 8) + 1, 256>>>(att, bgnn, batch);           // #5
    k_fc<<<GG, 256>>>(hy, Wfc, bfc, out);                      // #6
}